// round 15
// baseline (speedup 1.0000x reference)
#include <cuda_runtime.h>
#include <cuda_fp16.h>
#include <math.h>

#define NB 2
#define NP 8192
#define DD 64
#define KK 20
#define NS 4
#define CH (NP/NS)
#define TS 64
#define BUF 8
#define EPSB 1e-5f

// HMMA kNN params
#define KH 22           // per-half approximate top-K (margin over KK=20)
#define NSH 2           // candidate halves per query
#define HBUF 20         // append buffer depth

typedef unsigned long long u64;
typedef unsigned int u32;

// ---------------- scratch (device globals: allocation-free) ----------------
__device__ float d_hfT[(size_t)NB*NP*DD];     // fused features, point-major (B,N,64)
__device__ float d_sqn[(size_t)NB*NP];        // squared norms
__device__ float d_G  [(size_t)NB*NP*DD];     // W1 * h  (point-major)
__device__ float d_A  [(size_t)NB*NP*DD];     // (W2-W1) * h (point-major)
__device__ float d_xT [(size_t)NB*NP*4];      // x transposed+padded (B,N,4)
__device__ int   d_nidx[(size_t)NB*NP*KK];    // final knn indices
__device__ u64   d_scP[(size_t)NB*NP*NS*KK];  // layer-0 per-chunk packed lists
__device__ int   d_scI24[(size_t)NB*NP*NSH*KH]; // HMMA candidate indices
__device__ __half d_fhi[(size_t)NB*NP*DD];    // fp16 split hi
__device__ __half d_flo[(size_t)NB*NP*DD];    // fp16 split lo

// ---------------- helpers ----------------
union U64F2 { u64 u; float2 f; };

__device__ __forceinline__ u64 ffma2(u64 a, u64 b, u64 c) {
    u64 d;
    asm("fma.rn.f32x2 %0, %1, %2, %3;" : "=l"(d) : "l"(a), "l"(b), "l"(c));
    return d;
}
__device__ __forceinline__ u64 fadd2(u64 a, u64 b) {
    u64 d;
    asm("add.rn.f32x2 %0, %1, %2;" : "=l"(d) : "l"(a), "l"(b));
    return d;
}
__device__ __forceinline__ u64 packf2(float x, float y) {
    return (u64)__float_as_uint(x) | ((u64)__float_as_uint(y) << 32);
}
__device__ __forceinline__ u32 ford(float f) {
    u32 u = __float_as_uint(f);
    return (u & 0x80000000u) ? ~u : (u | 0x80000000u);
}

// cp.async helpers
__device__ __forceinline__ void cpa16(u32 dst, const void* src) {
    asm volatile("cp.async.cg.shared.global [%0], [%1], 16;"
                 :: "r"(dst), "l"(src) : "memory");
}
__device__ __forceinline__ void cpa4(u32 dst, const void* src) {
    asm volatile("cp.async.ca.shared.global [%0], [%1], 4;"
                 :: "r"(dst), "l"(src) : "memory");
}
#define CPA_COMMIT() asm volatile("cp.async.commit_group;" ::: "memory")
#define CPA_WAIT0()  asm volatile("cp.async.wait_group 0;" ::: "memory")

// indices in column-major smem, layer-0 path
__device__ __forceinline__ void insert_bf(float (&tv)[KK], int (*ti)[256],
                                          int tid, float v, int idx) {
    #pragma unroll
    for (int p = 0; p < KK; p++) {
        bool sw = v > tv[p];
        float nv = sw ? v : tv[p];
        float cv = sw ? tv[p] : v;
        int oi = ti[p][tid];
        int ni = sw ? idx : oi;
        int ci = sw ? oi : idx;
        tv[p] = nv; v = cv;
        ti[p][tid] = ni; idx = ci;
    }
}

// ---------------- HMMA helpers ----------------
__device__ __forceinline__ void ldm4(u32& r0, u32& r1, u32& r2, u32& r3, u32 addr) {
    asm volatile("ldmatrix.sync.aligned.m8n8.x4.shared.b16 {%0,%1,%2,%3},[%4];"
                 : "=r"(r0), "=r"(r1), "=r"(r2), "=r"(r3) : "r"(addr));
}
__device__ __forceinline__ void hmma(float* c, u32 a0, u32 a1, u32 a2, u32 a3,
                                     u32 b0, u32 b1) {
    asm volatile("mma.sync.aligned.m16n8k16.row.col.f32.f16.f16.f32 "
                 "{%0,%1,%2,%3},{%4,%5,%6,%7},{%8,%9},{%0,%1,%2,%3};"
                 : "+f"(c[0]), "+f"(c[1]), "+f"(c[2]), "+f"(c[3])
                 : "r"(a0), "r"(a1), "r"(a2), "r"(a3), "r"(b0), "r"(b1));
}

// smem layout for knnH; DPAD=68 (mult of 4 -> 16B-aligned v4 row scans)
#define DPAD    68
#define DWSTR   (32*DPAD*4)                 /* 8704 B per warp */
#define HB_B    0u                          /* 2 x 16KB B buffers */
#define HB_D    32768u                      /* + wid*DWSTR : 32 x 68 f32 keys */
#define HB_SQ   (32768u + 4u*DWSTR)         /* 67584: + sel*256 : 64 f32 */
#define HB_TBUF (HB_SQ + 512u)              /* 68096: HBUF x 128 thr x 8B */
#define SMEMH   (68096 + HBUF*128*8)        /* 88576 */

// ---------------- x -> xT (B,N,4) + squared norms ----------------
__global__ void prep_x_kernel(const float* __restrict__ x) {
    int i = blockIdx.x * blockDim.x + threadIdx.x;
    if (i >= NB*NP) return;
    int b = i >> 13, n = i & (NP - 1);
    const float* xb = x + (size_t)b * 3 * NP;
    float a0 = xb[0*NP + n], a1 = xb[1*NP + n], a2 = xb[2*NP + n];
    float4 v = make_float4(a0, a1, a2, 0.f);
    *reinterpret_cast<float4*>(d_xT + (size_t)i * 4) = v;
    d_sqn[i] = a0*a0 + a1*a1 + a2*a2;
}

// ---------------- layer0 G/A from x (W0 is 64x6) ----------------
__global__ void ga0_kernel(const float* __restrict__ W0) {
    int b = blockIdx.y;
    int n0 = blockIdx.x * 16;
    int o = threadIdx.x;         // 0..127
    float w0, w1, w2;
    if (o < 64) { w0 = W0[o*6+0]; w1 = W0[o*6+1]; w2 = W0[o*6+2]; }
    else { int u = o - 64;
           w0 = W0[u*6+3] - W0[u*6+0];
           w1 = W0[u*6+4] - W0[u*6+1];
           w2 = W0[u*6+5] - W0[u*6+2]; }
    float* dst = (o < 64) ? d_G : d_A;
    int oo = o & 63;
    #pragma unroll
    for (int p = 0; p < 16; p++) {
        float4 xv = *reinterpret_cast<const float4*>(d_xT + ((size_t)b*NP + n0 + p) * 4);
        float v = w0*xv.x + w1*xv.y + w2*xv.z;
        dst[((size_t)b*NP + n0 + p)*DD + oo] = v;
    }
}

// ---------------- layer-0 kNN (C=4 fp32 path, chunked) ----------------
template<int C>
__global__ void __launch_bounds__(256, 2) knn3_kernel() {
    const int b = blockIdx.z, s = blockIdx.y;
    const int tid = threadIdx.x;
    const int q = blockIdx.x * 256 + tid;
    const float* P = d_xT + (size_t)b * NP * C;

    __shared__ __align__(16) float smC[TS * C];
    __shared__ float smS[TS];
    __shared__ u64 sBuf[BUF][256];
    __shared__ int sTi[KK][256];

    u64 qp[C/2];
    #pragma unroll
    for (int j = 0; j < C/4; j++) {
        float4 v = *reinterpret_cast<const float4*>(P + (size_t)q * C + 4*j);
        qp[2*j]   = packf2(v.x, v.y);
        qp[2*j+1] = packf2(v.z, v.w);
    }

    float tv[KK];
    #pragma unroll
    for (int i = 0; i < KK; i++) { tv[i] = -INFINITY; sTi[i][tid] = 0x7FFFFFFF; }
    float thrK = -INFINITY;
    int cnt = 0;

    const u32 saTile = (u32)__cvta_generic_to_shared(smC);
    const u32 saBuf  = (u32)__cvta_generic_to_shared(sBuf) + tid * 8;

    for (int tile = 0; tile < CH / TS; tile++) {
        const int m0 = s * CH + tile * TS;
        __syncthreads();
        const float4* src = reinterpret_cast<const float4*>(P + (size_t)m0 * C);
        for (int t = tid; t < TS * C / 4; t += 256)
            reinterpret_cast<float4*>(smC)[t] = src[t];
        if (tid < TS) smS[tid] = d_sqn[b*NP + m0 + tid];
        __syncthreads();

        #pragma unroll 1
        for (int t = 0; t < TS; t++) {
            u32 ca = saTile + (u32)(t * C * 4);
            u64 x0, x1;
            asm("ld.shared.v2.b64 {%0,%1},[%2];" : "=l"(x0), "=l"(x1) : "r"(ca));
            U64F2 r; r.u = fadd2(ffma2(qp[0], x0, 0ull), ffma2(qp[1], x1, 0ull));
            float dot = r.f.x + r.f.y;
            float key = fmaf(2.0f, dot, -smS[t]);

            u64 pkd = ((u64)__float_as_uint(key) << 32) | (u32)(m0 + t);
            u32 addr = saBuf + (u32)cnt * (256u * 8u);
            asm volatile("{ .reg .pred p; setp.gt.f32 p, %1, %2;"
                         "  @p st.shared.b64 [%0], %3; }"
                         :: "r"(addr), "f"(key), "f"(thrK), "l"(pkd) : "memory");
            cnt += (key > thrK);

            if (__any_sync(0xffffffffu, cnt == BUF)) {
                #pragma unroll 1
                for (int e = 0; e < cnt; e++) {
                    u64 pk = sBuf[e][tid];
                    insert_bf(tv, sTi, tid,
                              __uint_as_float((u32)(pk >> 32)), (int)(u32)pk);
                }
                cnt = 0; thrK = tv[KK-1];
            }
        }
    }
    #pragma unroll 1
    for (int e = 0; e < cnt; e++) {
        u64 pk = sBuf[e][tid];
        insert_bf(tv, sTi, tid, __uint_as_float((u32)(pk >> 32)), (int)(u32)pk);
    }

    size_t off = ((size_t)(b*NP + q) * NS + s) * KK;
    #pragma unroll
    for (int i = 0; i < KK; i++)
        d_scP[off+i] = ((u64)ford(tv[i]) << 32) | (u32)(~(u32)sTi[i][tid]);
}

// ---------------- layer-0 merge ----------------
__global__ void merge_kernel() {
    int i = blockIdx.x * blockDim.x + threadIdx.x;
    if (i >= NB*NP) return;
    u64 tq[KK];
    #pragma unroll
    for (int k = 0; k < KK; k++) tq[k] = 0ull;
    const ulonglong2* src =
        reinterpret_cast<const ulonglong2*>(d_scP + (size_t)i * NS * KK);
    #pragma unroll 1
    for (int e = 0; e < NS*KK/2; e++) {
        ulonglong2 pr = src[e];
        #pragma unroll
        for (int h = 0; h < 2; h++) {
            u64 v = h ? pr.y : pr.x;
            if (v > tq[KK-1]) {
                #pragma unroll
                for (int p = 0; p < KK; p++) {
                    bool sw = v > tq[p];
                    u64 a = sw ? v : tq[p];
                    v = sw ? tq[p] : v;
                    tq[p] = a;
                }
            }
        }
    }
    #pragma unroll
    for (int k = 0; k < KK; k++)
        d_nidx[(size_t)i*KK + k] = (int)(~(u32)tq[k]);
}

// ---------------- HMMA kNN for C=64 layers (approximate top-22 per half) ----
// grid (NB*64, 2): blockIdx.y selects candidate half (4096 candidates).
// 128 threads; 3-pass fp16-split mma; cp.async double-buffered B tiles;
// keys into smem D tile; vectorized scan; packed-u64 register top-K.
__global__ void __launch_bounds__(128, 2) knnH_kernel() {
    extern __shared__ __align__(1024) char smem[];
    const int b   = blockIdx.x >> 6;
    const int qb  = blockIdx.x & 63;
    const int s   = blockIdx.y;
    const int tid = threadIdx.x;
    const int wid = tid >> 5;
    const int lane = tid & 31;
    const u32 sb = (u32)__cvta_generic_to_shared(smem);

    // ---- stage A (128 queries x 64ch, hi+lo) into [0,32KB), swizzled ----
    {
        const uint4* hs = reinterpret_cast<const uint4*>(d_fhi + ((size_t)b*NP + qb*128) * DD);
        const uint4* ls = reinterpret_cast<const uint4*>(d_flo + ((size_t)b*NP + qb*128) * DD);
        int row = tid;
        u32 sw = (u32)((row & 7) << 4);
        #pragma unroll
        for (int c2 = 0; c2 < 8; c2++) {
            u32 kb = (u32)(c2 * 16);
            *reinterpret_cast<uint4*>(smem + row*128 + (kb ^ sw)) = hs[row*8 + c2];
            *reinterpret_cast<uint4*>(smem + 16384 + row*128 + (kb ^ sw)) = ls[row*8 + c2];
        }
    }
    __syncthreads();

    // ---- extract A fragments ----
    u32 Ah[2][4][4], Al[2][4][4];
    {
        int mat = lane >> 3, r = lane & 7;
        int qrow = wid*32 + (mat & 1)*8 + r;
        u32 kadd = (mat >= 2) ? 16u : 0u;
        #pragma unroll
        for (int mt = 0; mt < 2; mt++) {
            int row = qrow + mt*16;
            u32 sw = (u32)((row & 7) << 4);
            #pragma unroll
            for (int ks = 0; ks < 4; ks++) {
                u32 kb = (u32)(ks*32) + kadd;
                u32 ah = sb + (u32)row*128u + (kb ^ sw);
                u32 al = ah + 16384u;
                ldm4(Ah[mt][ks][0], Ah[mt][ks][1], Ah[mt][ks][2], Ah[mt][ks][3], ah);
                ldm4(Al[mt][ks][0], Al[mt][ks][1], Al[mt][ks][2], Al[mt][ks][3], al);
            }
        }
    }
    __syncthreads();   // A region free; B buffers may overwrite

    // ---- top-k state: packed u64 (ord(key)<<32 | ~idx), register-resident ----
    u64 tq[KH];
    #pragma unroll
    for (int i = 0; i < KH; i++) tq[i] = 0ull;
    u64 thrU = 0ull;
    int cnt = 0;
    const u32 bufA = sb + HB_TBUF + (u32)tid * 8u;

    // B ldmatrix invariants
    const int bcr = ((lane >> 4) & 1) * 8 + (lane & 7);
    const u32 bkadd = (u32)(((lane >> 3) & 1) * 16);
    const u32 bswz = (u32)((bcr & 7) << 4);

    // prefetch mapping: row = tid>>1, half = tid&1 (64B = 4 x 16B)
    const int pfRow = tid >> 1;
    const int pfHalf = tid & 1;
    const u32 pfSw = (u32)((pfRow & 7) << 4);
    const int candBase = b*NP + s*4096;

    // ---- load chunk 0 via cp.async ----
    {
        const char* hs = (const char*)(d_fhi + ((size_t)candBase + pfRow) * DD);
        const char* ls = (const char*)(d_flo + ((size_t)candBase + pfRow) * DD);
        u32 dBH = sb + HB_B + (u32)pfRow*128u;
        u32 dBL = dBH + 64u*128u;
        #pragma unroll
        for (int c2 = 0; c2 < 4; c2++) {
            u32 kb = (u32)(pfHalf*64 + c2*16);
            cpa16(dBH + (kb ^ pfSw), hs + kb);
            cpa16(dBL + (kb ^ pfSw), ls + kb);
        }
        if (tid < 64) cpa4(sb + HB_SQ + (u32)tid*4u, &d_sqn[candBase + tid]);
        CPA_COMMIT();
        CPA_WAIT0();
    }
    __syncthreads();

    const u32 dBase = sb + HB_D + (u32)wid * (u32)DWSTR;

    #pragma unroll 1
    for (int c = 0; c < 64; c++) {
        const int sel = c & 1;
        const u32 bB = sb + HB_B + (u32)sel * 16384u;

        // ---- prefetch next chunk via cp.async (overlaps MMA) ----
        const int nc = c + 1;
        if (nc < 64) {
            const char* hs = (const char*)(d_fhi + ((size_t)candBase + nc*64 + pfRow) * DD);
            const char* ls = (const char*)(d_flo + ((size_t)candBase + nc*64 + pfRow) * DD);
            u32 dBH = sb + HB_B + (u32)((nc & 1) * 16384) + (u32)pfRow*128u;
            u32 dBL = dBH + 64u*128u;
            #pragma unroll
            for (int c2 = 0; c2 < 4; c2++) {
                u32 kb = (u32)(pfHalf*64 + c2*16);
                cpa16(dBH + (kb ^ pfSw), hs + kb);
                cpa16(dBL + (kb ^ pfSw), ls + kb);
            }
            if (tid < 64)
                cpa4(sb + HB_SQ + (u32)((nc & 1) * 256) + (u32)tid*4u,
                     &d_sqn[candBase + nc*64 + tid]);
            CPA_COMMIT();
        }

        // ---- MMA: acc = Ahi*Bhi + Alo*Bhi + Ahi*Blo ----
        float acc[2][8][4];
        #pragma unroll
        for (int mt = 0; mt < 2; mt++)
            #pragma unroll
            for (int nt = 0; nt < 8; nt++)
                #pragma unroll
                for (int e = 0; e < 4; e++) acc[mt][nt][e] = 0.f;

        #pragma unroll
        for (int ks = 0; ks < 4; ks++) {
            u32 kb = (u32)(ks*32) + bkadd;
            u32 bh[4][4];
            #pragma unroll
            for (int p = 0; p < 4; p++) {
                int row = p*16 + bcr;
                u32 a = bB + (u32)row*128u + (kb ^ bswz);
                ldm4(bh[p][0], bh[p][1], bh[p][2], bh[p][3], a);
            }
            #pragma unroll
            for (int mt = 0; mt < 2; mt++)
                #pragma unroll
                for (int p = 0; p < 4; p++) {
                    hmma(acc[mt][2*p],   Ah[mt][ks][0], Ah[mt][ks][1], Ah[mt][ks][2], Ah[mt][ks][3], bh[p][0], bh[p][1]);
                    hmma(acc[mt][2*p+1], Ah[mt][ks][0], Ah[mt][ks][1], Ah[mt][ks][2], Ah[mt][ks][3], bh[p][2], bh[p][3]);
                    hmma(acc[mt][2*p],   Al[mt][ks][0], Al[mt][ks][1], Al[mt][ks][2], Al[mt][ks][3], bh[p][0], bh[p][1]);
                    hmma(acc[mt][2*p+1], Al[mt][ks][0], Al[mt][ks][1], Al[mt][ks][2], Al[mt][ks][3], bh[p][2], bh[p][3]);
                }
            u32 bl[4][4];
            #pragma unroll
            for (int p = 0; p < 4; p++) {
                int row = 64 + p*16 + bcr;
                u32 a = bB + (u32)row*128u + (kb ^ bswz);
                ldm4(bl[p][0], bl[p][1], bl[p][2], bl[p][3], a);
            }
            #pragma unroll
            for (int mt = 0; mt < 2; mt++)
                #pragma unroll
                for (int p = 0; p < 4; p++) {
                    hmma(acc[mt][2*p],   Ah[mt][ks][0], Ah[mt][ks][1], Ah[mt][ks][2], Ah[mt][ks][3], bl[p][0], bl[p][1]);
                    hmma(acc[mt][2*p+1], Ah[mt][ks][0], Ah[mt][ks][1], Ah[mt][ks][2], Ah[mt][ks][3], bl[p][2], bl[p][3]);
                }
        }

        // ---- epilogue: key = fma(2, acc, -sqc) -> D tile ----
        {
            int g = lane >> 2, t4 = lane & 3;
            const u32 sqA = sb + HB_SQ + (u32)sel*256u;
            #pragma unroll
            for (int nt = 0; nt < 8; nt++) {
                int col = nt*8 + 2*t4;
                float2 sqc;
                asm("ld.shared.v2.f32 {%0,%1},[%2];"
                    : "=f"(sqc.x), "=f"(sqc.y) : "r"(sqA + (u32)col*4u));
                #pragma unroll
                for (int mt = 0; mt < 2; mt++) {
                    int row = mt*16 + g;
                    float k0 = fmaf(2.f, acc[mt][nt][0], -sqc.x);
                    float k1 = fmaf(2.f, acc[mt][nt][1], -sqc.y);
                    float k2 = fmaf(2.f, acc[mt][nt][2], -sqc.x);
                    float k3 = fmaf(2.f, acc[mt][nt][3], -sqc.y);
                    u32 a0 = dBase + (u32)(row*DPAD + col)*4u;
                    u32 a1 = dBase + (u32)((row+8)*DPAD + col)*4u;
                    asm volatile("st.shared.v2.f32 [%0],{%1,%2};"
                                 :: "r"(a0), "f"(k0), "f"(k1) : "memory");
                    asm volatile("st.shared.v2.f32 [%0],{%1,%2};"
                                 :: "r"(a1), "f"(k2), "f"(k3) : "memory");
                }
            }
        }
        __syncwarp();

        // ---- scan own query row: v4 loads, branch-free appends ----
        {
            const u32 rowA = dBase + (u32)(lane*DPAD)*4u;
            const int mB = s*4096 + c*64;
            #pragma unroll
            for (int jb = 0; jb < 4; jb++) {
                #pragma unroll
                for (int jg = 0; jg < 4; jg++) {
                    const int j = jb*16 + jg*4;
                    float k0, k1, k2, k3;
                    asm("ld.shared.v4.f32 {%0,%1,%2,%3},[%4];"
                        : "=f"(k0), "=f"(k1), "=f"(k2), "=f"(k3)
                        : "r"(rowA + (u32)j*4u));
                    #pragma unroll
                    for (int e = 0; e < 4; e++) {
                        float kv = (e==0)?k0:(e==1)?k1:(e==2)?k2:k3;
                        u64 pkd = ((u64)ford(kv) << 32) | (u32)(~(u32)(mB + j + e));
                        u32 addr = bufA + (u32)cnt * 1024u;
                        asm volatile("{ .reg .pred p; setp.gt.u64 p, %1, %2;"
                                     "  @p st.shared.b64 [%0], %1; }"
                                     :: "r"(addr), "l"(pkd), "l"(thrU) : "memory");
                        cnt += (pkd > thrU);
                    }
                }
                if (__any_sync(0xffffffffu, cnt >= 5)) {
                    #pragma unroll 1
                    for (int e = 0; e < cnt; e++) {
                        u64 v;
                        asm("ld.shared.b64 %0,[%1];" : "=l"(v) : "r"(bufA + (u32)e * 1024u));
                        #pragma unroll
                        for (int p = 0; p < KH; p++) {
                            bool sw = v > tq[p];
                            u64 a = sw ? v : tq[p];
                            v = sw ? tq[p] : v;
                            tq[p] = a;
                        }
                    }
                    cnt = 0; thrU = tq[KH-1];
                }
            }
        }

        // ---- wait for prefetched chunk, then flip ----
        if (nc < 64) CPA_WAIT0();
        __syncthreads();
    }

    // final flush
    #pragma unroll 1
    for (int e = 0; e < cnt; e++) {
        u64 v;
        asm("ld.shared.b64 %0,[%1];" : "=l"(v) : "r"(bufA + (u32)e * 1024u));
        #pragma unroll
        for (int p = 0; p < KH; p++) {
            bool sw = v > tq[p];
            u64 a = sw ? v : tq[p];
            v = sw ? tq[p] : v;
            tq[p] = a;
        }
    }

    const size_t q = (size_t)b*NP + qb*128 + tid;
    #pragma unroll
    for (int k = 0; k < KH; k++)
        d_scI24[(q*NSH + s)*KH + k] = (int)(~(u32)tq[k]);
}

// ---------------- rerank: exact fp32 top-20 over 44 HMMA candidates --------
__global__ void __launch_bounds__(128) rerank_kernel() {
    const int i = blockIdx.x * 128 + threadIdx.x;   // b*NP+n
    const int b = i >> 13;

    u64 qp[32];
    {
        const ulonglong2* qr = reinterpret_cast<const ulonglong2*>(d_hfT + (size_t)i * DD);
        #pragma unroll
        for (int j = 0; j < 16; j++) { ulonglong2 w = qr[j]; qp[2*j] = w.x; qp[2*j+1] = w.y; }
    }

    float tv[KK]; int ti[KK];
    #pragma unroll
    for (int k = 0; k < KK; k++) { tv[k] = -INFINITY; ti[k] = 0x7FFFFFFF; }

    const size_t base = (size_t)i * NSH * KH;
    #pragma unroll 1
    for (int e = 0; e < NSH*KH; e++) {
        int idx = d_scI24[base + e];
        const ulonglong2* cr =
            reinterpret_cast<const ulonglong2*>(d_hfT + ((size_t)(b*NP) + idx) * DD);
        u64 a0 = 0ull, a1 = 0ull, a2 = 0ull, a3 = 0ull;
        #pragma unroll
        for (int j = 0; j < 16; j++) {          // FULL 64 channels (16 x 16B)
            ulonglong2 w = cr[j];
            if ((j & 1) == 0) { a0 = ffma2(qp[2*j], w.x, a0); a1 = ffma2(qp[2*j+1], w.y, a1); }
            else              { a2 = ffma2(qp[2*j], w.x, a2); a3 = ffma2(qp[2*j+1], w.y, a3); }
        }
        U64F2 r; r.u = fadd2(fadd2(a0, a1), fadd2(a2, a3));
        float dot = r.f.x + r.f.y;
        float v = fmaf(2.f, dot, -d_sqn[b*NP + idx]);

        // total-order insert: (value desc, index asc)
        #pragma unroll
        for (int p = 0; p < KK; p++) {
            bool sw = (v > tv[p]) || (v == tv[p] && idx < ti[p]);
            float ov = tv[p]; int oi = ti[p];
            tv[p] = sw ? v : ov;  ti[p] = sw ? idx : oi;
            v = sw ? ov : v;      idx = sw ? oi : idx;
        }
    }
    #pragma unroll
    for (int k = 0; k < KK; k++) d_nidx[(size_t)i*KK + k] = ti[k];
}

// ---------------- gather-max + BN + lrelu -> h (channel-major output) ------
__global__ void gather_kernel(const float* __restrict__ gamma,
                              const float* __restrict__ beta,
                              const float* __restrict__ mean,
                              const float* __restrict__ var,
                              float* __restrict__ out) {
    int b = blockIdx.y;
    int j = threadIdx.x >> 6;
    int o = threadIdx.x & 63;
    int n = blockIdx.x * 4 + j;

    __shared__ int sIdx[4 * KK];
    if (threadIdx.x < 4 * KK) {
        int jj = threadIdx.x / KK, kk = threadIdx.x % KK;
        sIdx[threadIdx.x] = d_nidx[((size_t)b*NP + blockIdx.x*4 + jj)*KK + kk];
    }
    __syncthreads();

    const float* Gb = d_G + (size_t)b * NP * DD;
    float mx = -INFINITY;
    #pragma unroll
    for (int k = 0; k < KK; k++)
        mx = fmaxf(mx, Gb[(size_t)sIdx[j*KK + k] * DD + o]);

    float z = d_A[((size_t)b*NP + n)*DD + o] + mx;
    float sc = gamma[o] * rsqrtf(var[o] + EPSB);
    z = (z - mean[o]) * sc + beta[o];
    z = (z >= 0.f) ? z : 0.2f * z;
    out[((size_t)b*DD + o)*NP + n] = z;
}

// ---------------- fuse: hf = elu(Wf * [h; rep]) -> point-major ----------------
__global__ void fuse_kernel(const float* __restrict__ h,
                            const float* __restrict__ rep,
                            const float* __restrict__ W) {
    int b = blockIdx.y;
    int n0 = blockIdx.x * 16;
    int o = threadIdx.x;

    __shared__ float sWT[128][64];
    __shared__ float sIn[128][16];
    for (int t = threadIdx.x; t < 128*64; t += 64) {
        int c = t >> 6, oo = t & 63;
        sWT[c][oo] = W[oo*128 + c];
    }
    for (int t = threadIdx.x; t < 128*16; t += 64) {
        int c = t >> 4, p = t & 15;
        sIn[c][p] = (c < 64) ? h  [((size_t)b*DD + c)*NP + n0 + p]
                             : rep[((size_t)b*DD + (c-64))*NP + n0 + p];
    }
    __syncthreads();

    float acc[16];
    #pragma unroll
    for (int p = 0; p < 16; p++) acc[p] = 0.f;
    for (int c = 0; c < 128; c++) {
        float w = sWT[c][o];
        #pragma unroll
        for (int p = 0; p < 16; p++) acc[p] = fmaf(w, sIn[c][p], acc[p]);
    }
    #pragma unroll
    for (int p = 0; p < 16; p++) {
        float z = acc[p];
        z = (z > 0.f) ? z : expm1f(z);
        d_hfT[((size_t)b*NP + n0 + p)*DD + o] = z;
    }
}

// ---------------- sqnorm + fp16 hi/lo split of hfT ----------------
__global__ void sqsplit_kernel() {
    int i = blockIdx.x * blockDim.x + threadIdx.x;
    if (i >= NB*NP) return;
    const float4* r = reinterpret_cast<const float4*>(d_hfT + (size_t)i * DD);
    uint2* hiDst = reinterpret_cast<uint2*>(d_fhi + (size_t)i * DD);
    uint2* loDst = reinterpret_cast<uint2*>(d_flo + (size_t)i * DD);
    float s = 0.f;
    #pragma unroll
    for (int j = 0; j < 16; j++) {
        float4 v = r[j];
        s += v.x*v.x + v.y*v.y + v.z*v.z + v.w*v.w;
        float vv[4] = {v.x, v.y, v.z, v.w};
        unsigned short h[4], l[4];
        #pragma unroll
        for (int e = 0; e < 4; e++) {
            __half hb = __float2half(vv[e]);
            __half lb = __float2half(vv[e] - __half2float(hb));
            h[e] = __half_as_ushort(hb);
            l[e] = __half_as_ushort(lb);
        }
        uint2 hp, lp;
        hp.x = (u32)h[0] | ((u32)h[1] << 16); hp.y = (u32)h[2] | ((u32)h[3] << 16);
        lp.x = (u32)l[0] | ((u32)l[1] << 16); lp.y = (u32)l[2] | ((u32)l[3] << 16);
        hiDst[j] = hp; loDst[j] = lp;
    }
    d_sqn[i] = s;
}

// ---------------- G/A from hfT (W is 64x128) ----------------
__global__ void ga_kernel(const float* __restrict__ W) {
    int b = blockIdx.y;
    int n0 = blockIdx.x * 16;
    int o = threadIdx.x;

    __shared__ float sWT[64][128];
    __shared__ float sIn[16][64];
    for (int c = 0; c < 64; c++) {
        float w = (o < 64) ? W[o*128 + c]
                           : (W[(o-64)*128 + 64 + c] - W[(o-64)*128 + c]);
        sWT[c][o] = w;
    }
    for (int t = threadIdx.x; t < 16*64; t += 128) {
        int p = t >> 6, c = t & 63;
        sIn[p][c] = d_hfT[((size_t)b*NP + n0 + p)*DD + c];
    }
    __syncthreads();

    float acc[16];
    #pragma unroll
    for (int p = 0; p < 16; p++) acc[p] = 0.f;
    for (int c = 0; c < 64; c++) {
        float w = sWT[c][o];
        #pragma unroll
        for (int p = 0; p < 16; p++) acc[p] = fmaf(w, sIn[p][c], acc[p]);
    }
    float* dst = (o < 64) ? d_G : d_A;
    int oo = o & 63;
    #pragma unroll
    for (int p = 0; p < 16; p++)
        dst[((size_t)b*NP + n0 + p)*DD + oo] = acc[p];
}

// ---------------- launch ----------------
extern "C" void kernel_launch(void* const* d_in, const int* in_sizes, int n_in,
                              void* d_out, int out_size) {
    (void)in_sizes; (void)n_in; (void)out_size;
    const float* x     = (const float*)d_in[0];
    const float* reps  = (const float*)d_in[1];
    const float* w0    = (const float*)d_in[2];
    const float* convw = (const float*)d_in[3];
    const float* gam   = (const float*)d_in[4];
    const float* bet   = (const float*)d_in[5];
    const float* rm    = (const float*)d_in[6];
    const float* rv    = (const float*)d_in[7];
    const float* fw    = (const float*)d_in[8];
    float* out = (float*)d_out;
    const size_t LSZ = (size_t)NB * DD * NP;

    cudaFuncSetAttribute(knnH_kernel,
                         cudaFuncAttributeMaxDynamicSharedMemorySize, SMEMH);

    // layer 0 (fp32 path)
    prep_x_kernel<<<NB*NP/256, 256>>>(x);
    ga0_kernel<<<dim3(NP/16, NB), 128>>>(w0);
    knn3_kernel<4><<<dim3(NP/256, NS, NB), 256>>>();
    merge_kernel<<<NB*NP/256, 256>>>();
    gather_kernel<<<dim3(NP/4, NB), 256>>>(gam, bet, rm, rv, out);

    // layers 1..3 (HMMA candidates + exact fp32 rerank)
    for (int i = 0; i < 3; i++) {
        fuse_kernel<<<dim3(NP/16, NB), 64>>>(out + (size_t)i * LSZ,
                                             reps + (size_t)i * LSZ,
                                             fw + (size_t)i * 64 * 128);
        sqsplit_kernel<<<NB*NP/256, 256>>>();
        ga_kernel<<<dim3(NP/16, NB), 128>>>(convw + (size_t)i * 64 * 128);
        knnH_kernel<<<dim3(NB*64, NSH), 128, SMEMH>>>();
        rerank_kernel<<<NB*NP/128, 128>>>();
        gather_kernel<<<dim3(NP/4, NB), 256>>>(gam + (i+1)*64, bet + (i+1)*64,
                                               rm + (i+1)*64, rv + (i+1)*64,
                                               out + (size_t)(i+1) * LSZ);
    }
}

// round 16
// speedup vs baseline: 1.1080x; 1.1080x over previous
#include <cuda_runtime.h>
#include <cuda_fp16.h>
#include <math.h>

#define NB 2
#define NP 8192
#define DD 64
#define KK 20
#define NS 4
#define CH (NP/NS)
#define TS 64
#define BUF 8
#define EPSB 1e-5f

// HMMA kNN params
#define KH 24           // per-half approximate top-K (margin over KK=20)
#define NSH 2           // candidate halves per query
#define HBUF 20         // append buffer depth

typedef unsigned long long u64;
typedef unsigned int u32;

// ---------------- scratch (device globals: allocation-free) ----------------
__device__ float d_hfT[(size_t)NB*NP*DD];     // fused features, point-major (B,N,64)
__device__ float d_sqn[(size_t)NB*NP];        // squared norms
__device__ float d_G  [(size_t)NB*NP*DD];     // W1 * h  (point-major)
__device__ float d_A  [(size_t)NB*NP*DD];     // (W2-W1) * h (point-major)
__device__ float d_xT [(size_t)NB*NP*4];      // x transposed+padded (B,N,4)
__device__ int   d_nidx[(size_t)NB*NP*KK];    // final knn indices
__device__ u64   d_scP[(size_t)NB*NP*NS*KK];  // layer-0 per-chunk packed lists
__device__ int   d_scI24[(size_t)NB*NP*NSH*KH]; // HMMA candidate indices
__device__ __half d_fhi[(size_t)NB*NP*DD];    // fp16 split hi
__device__ __half d_flo[(size_t)NB*NP*DD];    // fp16 split lo

// ---------------- helpers ----------------
union U64F2 { u64 u; float2 f; };

__device__ __forceinline__ u64 ffma2(u64 a, u64 b, u64 c) {
    u64 d;
    asm("fma.rn.f32x2 %0, %1, %2, %3;" : "=l"(d) : "l"(a), "l"(b), "l"(c));
    return d;
}
__device__ __forceinline__ u64 fadd2(u64 a, u64 b) {
    u64 d;
    asm("add.rn.f32x2 %0, %1, %2;" : "=l"(d) : "l"(a), "l"(b));
    return d;
}
__device__ __forceinline__ u64 packf2(float x, float y) {
    return (u64)__float_as_uint(x) | ((u64)__float_as_uint(y) << 32);
}
__device__ __forceinline__ u32 ford(float f) {
    u32 u = __float_as_uint(f);
    return (u & 0x80000000u) ? ~u : (u | 0x80000000u);
}

// indices in column-major smem, layer-0 path
__device__ __forceinline__ void insert_bf(float (&tv)[KK], int (*ti)[256],
                                          int tid, float v, int idx) {
    #pragma unroll
    for (int p = 0; p < KK; p++) {
        bool sw = v > tv[p];
        float nv = sw ? v : tv[p];
        float cv = sw ? tv[p] : v;
        int oi = ti[p][tid];
        int ni = sw ? idx : oi;
        int ci = sw ? oi : idx;
        tv[p] = nv; v = cv;
        ti[p][tid] = ni; idx = ci;
    }
}
// HMMA path: values in regs, indices in smem at byte stride 128
__device__ __forceinline__ void insert_ti24(float (&tv)[KH], u32 tiB,
                                            float v, int idx) {
    #pragma unroll
    for (int p = 0; p < KH; p++) {
        bool sw = v > tv[p];
        int oi;
        asm volatile("ld.shared.b32 %0,[%1];" : "=r"(oi) : "r"(tiB + p*128u));
        int ni = sw ? idx : oi;
        asm volatile("st.shared.b32 [%0],%1;" :: "r"(tiB + p*128u), "r"(ni) : "memory");
        idx = sw ? oi : idx;
        float ov = tv[p]; tv[p] = sw ? v : ov; v = sw ? ov : v;
    }
}

// ---------------- HMMA helpers ----------------
__device__ __forceinline__ void ldm4(u32& r0, u32& r1, u32& r2, u32& r3, u32 addr) {
    asm volatile("ldmatrix.sync.aligned.m8n8.x4.shared.b16 {%0,%1,%2,%3},[%4];"
                 : "=r"(r0), "=r"(r1), "=r"(r2), "=r"(r3) : "r"(addr));
}
__device__ __forceinline__ void hmma(float* c, u32 a0, u32 a1, u32 a2, u32 a3,
                                     u32 b0, u32 b1) {
    asm volatile("mma.sync.aligned.m16n8k16.row.col.f32.f16.f16.f32 "
                 "{%0,%1,%2,%3},{%4,%5,%6,%7},{%8,%9},{%0,%1,%2,%3};"
                 : "+f"(c[0]), "+f"(c[1]), "+f"(c[2]), "+f"(c[3])
                 : "r"(a0), "r"(a1), "r"(a2), "r"(a3), "r"(b0), "r"(b1));
}

// smem layout for knnH; DPAD=68 (mult of 4 -> 16B-aligned v4 row scans)
#define DPAD    68
#define DWSTR   (32*DPAD*4)                 /* 8704 B per warp */
#define HB_B    0u                          /* 2 x 16KB B buffers */
#define HB_D    32768u                      /* + wid*DWSTR : 32 x 68 f32 keys */
#define HB_SQ   (32768u + 4u*DWSTR)         /* 67584: + sel*256 : 64 f32 */
#define HB_TBUF (HB_SQ + 512u)              /* 68096: HBUF x 128 thr x 8B */
#define HB_TI   (HB_TBUF + HBUF*128u*8u)    /* 88576: 4 warps x 24 x 32 x 4B */
#define SMEMH   (88576 + 4*KH*32*4)         /* 100864 */

// ---------------- x -> xT (B,N,4) + squared norms ----------------
__global__ void prep_x_kernel(const float* __restrict__ x) {
    int i = blockIdx.x * blockDim.x + threadIdx.x;
    if (i >= NB*NP) return;
    int b = i >> 13, n = i & (NP - 1);
    const float* xb = x + (size_t)b * 3 * NP;
    float a0 = xb[0*NP + n], a1 = xb[1*NP + n], a2 = xb[2*NP + n];
    float4 v = make_float4(a0, a1, a2, 0.f);
    *reinterpret_cast<float4*>(d_xT + (size_t)i * 4) = v;
    d_sqn[i] = a0*a0 + a1*a1 + a2*a2;
}

// ---------------- layer0 G/A from x (W0 is 64x6) ----------------
__global__ void ga0_kernel(const float* __restrict__ W0) {
    int b = blockIdx.y;
    int n0 = blockIdx.x * 16;
    int o = threadIdx.x;         // 0..127
    float w0, w1, w2;
    if (o < 64) { w0 = W0[o*6+0]; w1 = W0[o*6+1]; w2 = W0[o*6+2]; }
    else { int u = o - 64;
           w0 = W0[u*6+3] - W0[u*6+0];
           w1 = W0[u*6+4] - W0[u*6+1];
           w2 = W0[u*6+5] - W0[u*6+2]; }
    float* dst = (o < 64) ? d_G : d_A;
    int oo = o & 63;
    #pragma unroll
    for (int p = 0; p < 16; p++) {
        float4 xv = *reinterpret_cast<const float4*>(d_xT + ((size_t)b*NP + n0 + p) * 4);
        float v = w0*xv.x + w1*xv.y + w2*xv.z;
        dst[((size_t)b*NP + n0 + p)*DD + oo] = v;
    }
}

// ---------------- layer-0 kNN (C=4 fp32 path, chunked) ----------------
template<int C>
__global__ void __launch_bounds__(256, 2) knn3_kernel() {
    const int b = blockIdx.z, s = blockIdx.y;
    const int tid = threadIdx.x;
    const int q = blockIdx.x * 256 + tid;
    const float* P = d_xT + (size_t)b * NP * C;

    __shared__ __align__(16) float smC[TS * C];
    __shared__ float smS[TS];
    __shared__ u64 sBuf[BUF][256];
    __shared__ int sTi[KK][256];

    u64 qp[C/2];
    #pragma unroll
    for (int j = 0; j < C/4; j++) {
        float4 v = *reinterpret_cast<const float4*>(P + (size_t)q * C + 4*j);
        qp[2*j]   = packf2(v.x, v.y);
        qp[2*j+1] = packf2(v.z, v.w);
    }

    float tv[KK];
    #pragma unroll
    for (int i = 0; i < KK; i++) { tv[i] = -INFINITY; sTi[i][tid] = 0x7FFFFFFF; }
    float thrK = -INFINITY;
    int cnt = 0;

    const u32 saTile = (u32)__cvta_generic_to_shared(smC);
    const u32 saBuf  = (u32)__cvta_generic_to_shared(sBuf) + tid * 8;

    for (int tile = 0; tile < CH / TS; tile++) {
        const int m0 = s * CH + tile * TS;
        __syncthreads();
        const float4* src = reinterpret_cast<const float4*>(P + (size_t)m0 * C);
        for (int t = tid; t < TS * C / 4; t += 256)
            reinterpret_cast<float4*>(smC)[t] = src[t];
        if (tid < TS) smS[tid] = d_sqn[b*NP + m0 + tid];
        __syncthreads();

        #pragma unroll 1
        for (int t = 0; t < TS; t++) {
            u32 ca = saTile + (u32)(t * C * 4);
            u64 x0, x1;
            asm("ld.shared.v2.b64 {%0,%1},[%2];" : "=l"(x0), "=l"(x1) : "r"(ca));
            U64F2 r; r.u = fadd2(ffma2(qp[0], x0, 0ull), ffma2(qp[1], x1, 0ull));
            float dot = r.f.x + r.f.y;
            float key = fmaf(2.0f, dot, -smS[t]);

            u64 pkd = ((u64)__float_as_uint(key) << 32) | (u32)(m0 + t);
            u32 addr = saBuf + (u32)cnt * (256u * 8u);
            asm volatile("{ .reg .pred p; setp.gt.f32 p, %1, %2;"
                         "  @p st.shared.b64 [%0], %3; }"
                         :: "r"(addr), "f"(key), "f"(thrK), "l"(pkd) : "memory");
            cnt += (key > thrK);

            if (__any_sync(0xffffffffu, cnt == BUF)) {
                #pragma unroll 1
                for (int e = 0; e < cnt; e++) {
                    u64 pk = sBuf[e][tid];
                    insert_bf(tv, sTi, tid,
                              __uint_as_float((u32)(pk >> 32)), (int)(u32)pk);
                }
                cnt = 0; thrK = tv[KK-1];
            }
        }
    }
    #pragma unroll 1
    for (int e = 0; e < cnt; e++) {
        u64 pk = sBuf[e][tid];
        insert_bf(tv, sTi, tid, __uint_as_float((u32)(pk >> 32)), (int)(u32)pk);
    }

    size_t off = ((size_t)(b*NP + q) * NS + s) * KK;
    #pragma unroll
    for (int i = 0; i < KK; i++)
        d_scP[off+i] = ((u64)ford(tv[i]) << 32) | (u32)(~(u32)sTi[i][tid]);
}

// ---------------- layer-0 merge ----------------
__global__ void merge_kernel() {
    int i = blockIdx.x * blockDim.x + threadIdx.x;
    if (i >= NB*NP) return;
    u64 tq[KK];
    #pragma unroll
    for (int k = 0; k < KK; k++) tq[k] = 0ull;
    const ulonglong2* src =
        reinterpret_cast<const ulonglong2*>(d_scP + (size_t)i * NS * KK);
    #pragma unroll 1
    for (int e = 0; e < NS*KK/2; e++) {
        ulonglong2 pr = src[e];
        #pragma unroll
        for (int h = 0; h < 2; h++) {
            u64 v = h ? pr.y : pr.x;
            if (v > tq[KK-1]) {
                #pragma unroll
                for (int p = 0; p < KK; p++) {
                    bool sw = v > tq[p];
                    u64 a = sw ? v : tq[p];
                    v = sw ? tq[p] : v;
                    tq[p] = a;
                }
            }
        }
    }
    #pragma unroll
    for (int k = 0; k < KK; k++)
        d_nidx[(size_t)i*KK + k] = (int)(~(u32)tq[k]);
}

// ---------------- HMMA kNN for C=64 layers (approximate top-24 per half) ----
// grid (NB*64, 2): blockIdx.y selects candidate half (4096 candidates).
// 128 threads; 3-pass fp16-split mma; keys into smem D tile; vectorized scan.
// (R14 structure, verbatim — measured best.)
__global__ void __launch_bounds__(128, 2) knnH_kernel() {
    extern __shared__ __align__(1024) char smem[];
    const int b   = blockIdx.x >> 6;
    const int qb  = blockIdx.x & 63;
    const int s   = blockIdx.y;
    const int tid = threadIdx.x;
    const int wid = tid >> 5;
    const int lane = tid & 31;
    const u32 sb = (u32)__cvta_generic_to_shared(smem);

    // ---- stage A (128 queries x 64ch, hi+lo) into [0,32KB), swizzled ----
    {
        const uint4* hs = reinterpret_cast<const uint4*>(d_fhi + ((size_t)b*NP + qb*128) * DD);
        const uint4* ls = reinterpret_cast<const uint4*>(d_flo + ((size_t)b*NP + qb*128) * DD);
        int row = tid;
        u32 sw = (u32)((row & 7) << 4);
        #pragma unroll
        for (int c2 = 0; c2 < 8; c2++) {
            u32 kb = (u32)(c2 * 16);
            *reinterpret_cast<uint4*>(smem + row*128 + (kb ^ sw)) = hs[row*8 + c2];
            *reinterpret_cast<uint4*>(smem + 16384 + row*128 + (kb ^ sw)) = ls[row*8 + c2];
        }
    }
    __syncthreads();

    // ---- extract A fragments ----
    u32 Ah[2][4][4], Al[2][4][4];
    {
        int mat = lane >> 3, r = lane & 7;
        int qrow = wid*32 + (mat & 1)*8 + r;
        u32 kadd = (mat >= 2) ? 16u : 0u;
        #pragma unroll
        for (int mt = 0; mt < 2; mt++) {
            int row = qrow + mt*16;
            u32 sw = (u32)((row & 7) << 4);
            #pragma unroll
            for (int ks = 0; ks < 4; ks++) {
                u32 kb = (u32)(ks*32) + kadd;
                u32 ah = sb + (u32)row*128u + (kb ^ sw);
                u32 al = ah + 16384u;
                ldm4(Ah[mt][ks][0], Ah[mt][ks][1], Ah[mt][ks][2], Ah[mt][ks][3], ah);
                ldm4(Al[mt][ks][0], Al[mt][ks][1], Al[mt][ks][2], Al[mt][ks][3], al);
            }
        }
    }
    __syncthreads();   // A region free; B buffers may overwrite

    // ---- top-k state: values in regs, indices in smem ----
    float tv[KH];
    const u32 tiB = sb + HB_TI + (u32)wid*(u32)(KH*32*4) + (u32)lane*4u;
    #pragma unroll
    for (int i = 0; i < KH; i++) {
        tv[i] = -INFINITY;
        asm volatile("st.shared.b32 [%0],%1;" :: "r"(tiB + i*128u), "r"(0x7FFFFFFF) : "memory");
    }
    float thr = -INFINITY;
    int cnt = 0;
    const u32 bufA = sb + HB_TBUF + (u32)tid * 8u;

    // B ldmatrix invariants
    const int bcr = ((lane >> 4) & 1) * 8 + (lane & 7);
    const u32 bkadd = (u32)(((lane >> 3) & 1) * 16);
    const u32 bswz = (u32)((bcr & 7) << 4);

    // prefetch mapping
    const int pfRow = tid >> 1;
    const int pfHalf = tid & 1;
    const u32 pfSw = (u32)((pfRow & 7) << 4);
    const int candBase = b*NP + s*4096;

    // ---- load chunk 0 ----
    {
        const uint4* hs = reinterpret_cast<const uint4*>(d_fhi + ((size_t)candBase + pfRow) * DD);
        const uint4* ls = reinterpret_cast<const uint4*>(d_flo + ((size_t)candBase + pfRow) * DD);
        #pragma unroll
        for (int c2 = 0; c2 < 4; c2++) {
            u32 kb = (u32)(pfHalf*64 + c2*16);
            *reinterpret_cast<uint4*>(smem + HB_B + pfRow*128 + (kb ^ pfSw)) = hs[pfHalf*4 + c2];
            *reinterpret_cast<uint4*>(smem + HB_B + (64+pfRow)*128 + (kb ^ pfSw)) = ls[pfHalf*4 + c2];
        }
        if (tid < 64)
            *reinterpret_cast<float*>(smem + HB_SQ + tid*4) = d_sqn[candBase + tid];
    }
    __syncthreads();

    const u32 dBase = sb + HB_D + (u32)wid * (u32)DWSTR;

    #pragma unroll 1
    for (int c = 0; c < 64; c++) {
        const int sel = c & 1;
        const u32 bB = sb + HB_B + (u32)sel * 16384u;

        // prefetch next chunk into registers
        uint4 pf[8]; float pfsq = 0.f;
        const int nc = c + 1;
        if (nc < 64) {
            const uint4* hs = reinterpret_cast<const uint4*>(d_fhi + ((size_t)candBase + nc*64 + pfRow) * DD);
            const uint4* ls = reinterpret_cast<const uint4*>(d_flo + ((size_t)candBase + nc*64 + pfRow) * DD);
            #pragma unroll
            for (int c2 = 0; c2 < 4; c2++) {
                pf[c2]   = hs[pfHalf*4 + c2];
                pf[4+c2] = ls[pfHalf*4 + c2];
            }
            if (tid < 64) pfsq = d_sqn[candBase + nc*64 + tid];
        }

        // ---- MMA: acc = Ahi*Bhi + Alo*Bhi + Ahi*Blo ----
        float acc[2][8][4];
        #pragma unroll
        for (int mt = 0; mt < 2; mt++)
            #pragma unroll
            for (int nt = 0; nt < 8; nt++)
                #pragma unroll
                for (int e = 0; e < 4; e++) acc[mt][nt][e] = 0.f;

        #pragma unroll
        for (int ks = 0; ks < 4; ks++) {
            u32 kb = (u32)(ks*32) + bkadd;
            u32 bh[4][4];
            #pragma unroll
            for (int p = 0; p < 4; p++) {
                int row = p*16 + bcr;
                u32 a = bB + (u32)row*128u + (kb ^ bswz);
                ldm4(bh[p][0], bh[p][1], bh[p][2], bh[p][3], a);
            }
            #pragma unroll
            for (int mt = 0; mt < 2; mt++)
                #pragma unroll
                for (int p = 0; p < 4; p++) {
                    hmma(acc[mt][2*p],   Ah[mt][ks][0], Ah[mt][ks][1], Ah[mt][ks][2], Ah[mt][ks][3], bh[p][0], bh[p][1]);
                    hmma(acc[mt][2*p+1], Ah[mt][ks][0], Ah[mt][ks][1], Ah[mt][ks][2], Ah[mt][ks][3], bh[p][2], bh[p][3]);
                    hmma(acc[mt][2*p],   Al[mt][ks][0], Al[mt][ks][1], Al[mt][ks][2], Al[mt][ks][3], bh[p][0], bh[p][1]);
                    hmma(acc[mt][2*p+1], Al[mt][ks][0], Al[mt][ks][1], Al[mt][ks][2], Al[mt][ks][3], bh[p][2], bh[p][3]);
                }
            u32 bl[4][4];
            #pragma unroll
            for (int p = 0; p < 4; p++) {
                int row = 64 + p*16 + bcr;
                u32 a = bB + (u32)row*128u + (kb ^ bswz);
                ldm4(bl[p][0], bl[p][1], bl[p][2], bl[p][3], a);
            }
            #pragma unroll
            for (int mt = 0; mt < 2; mt++)
                #pragma unroll
                for (int p = 0; p < 4; p++) {
                    hmma(acc[mt][2*p],   Ah[mt][ks][0], Ah[mt][ks][1], Ah[mt][ks][2], Ah[mt][ks][3], bl[p][0], bl[p][1]);
                    hmma(acc[mt][2*p+1], Ah[mt][ks][0], Ah[mt][ks][1], Ah[mt][ks][2], Ah[mt][ks][3], bl[p][2], bl[p][3]);
                }
        }

        // ---- epilogue: key = fma(2, acc, -sqc) -> D tile ----
        {
            int g = lane >> 2, t4 = lane & 3;
            const u32 sqA = sb + HB_SQ + (u32)sel*256u;
            #pragma unroll
            for (int nt = 0; nt < 8; nt++) {
                int col = nt*8 + 2*t4;
                float2 sqc;
                asm("ld.shared.v2.f32 {%0,%1},[%2];"
                    : "=f"(sqc.x), "=f"(sqc.y) : "r"(sqA + (u32)col*4u));
                #pragma unroll
                for (int mt = 0; mt < 2; mt++) {
                    int row = mt*16 + g;
                    float k0 = fmaf(2.f, acc[mt][nt][0], -sqc.x);
                    float k1 = fmaf(2.f, acc[mt][nt][1], -sqc.y);
                    float k2 = fmaf(2.f, acc[mt][nt][2], -sqc.x);
                    float k3 = fmaf(2.f, acc[mt][nt][3], -sqc.y);
                    u32 a0 = dBase + (u32)(row*DPAD + col)*4u;
                    u32 a1 = dBase + (u32)((row+8)*DPAD + col)*4u;
                    asm volatile("st.shared.v2.f32 [%0],{%1,%2};"
                                 :: "r"(a0), "f"(k0), "f"(k1) : "memory");
                    asm volatile("st.shared.v2.f32 [%0],{%1,%2};"
                                 :: "r"(a1), "f"(k2), "f"(k3) : "memory");
                }
            }
        }
        __syncwarp();

        // ---- scan own query row: v4 loads, branch-free appends ----
        {
            const u32 rowA = dBase + (u32)(lane*DPAD)*4u;
            const int mB = s*4096 + c*64;
            #pragma unroll
            for (int jb = 0; jb < 4; jb++) {
                #pragma unroll
                for (int jg = 0; jg < 4; jg++) {
                    const int j = jb*16 + jg*4;
                    float k0, k1, k2, k3;
                    asm("ld.shared.v4.f32 {%0,%1,%2,%3},[%4];"
                        : "=f"(k0), "=f"(k1), "=f"(k2), "=f"(k3)
                        : "r"(rowA + (u32)j*4u));
                    #pragma unroll
                    for (int e = 0; e < 4; e++) {
                        float kv = (e==0)?k0:(e==1)?k1:(e==2)?k2:k3;
                        u64 pkd = ((u64)__float_as_uint(kv) << 32) | (u32)(mB + j + e);
                        u32 addr = bufA + (u32)cnt * 1024u;
                        asm volatile("{ .reg .pred p; setp.gt.f32 p, %1, %2;"
                                     "  @p st.shared.b64 [%0], %3; }"
                                     :: "r"(addr), "f"(kv), "f"(thr), "l"(pkd) : "memory");
                        cnt += (kv > thr);
                    }
                }
                if (__any_sync(0xffffffffu, cnt >= 4)) {
                    #pragma unroll 1
                    for (int e = 0; e < cnt; e++) {
                        u64 pk;
                        asm("ld.shared.b64 %0,[%1];" : "=l"(pk) : "r"(bufA + (u32)e * 1024u));
                        insert_ti24(tv, tiB, __uint_as_float((u32)(pk >> 32)), (int)(u32)pk);
                    }
                    cnt = 0; thr = tv[KH-1];
                }
            }
        }

        // ---- store prefetched chunk ----
        if (nc < 64) {
            char* dB = smem + HB_B + ((nc & 1) ? 16384 : 0);
            #pragma unroll
            for (int c2 = 0; c2 < 4; c2++) {
                u32 kb = (u32)(pfHalf*64 + c2*16);
                *reinterpret_cast<uint4*>(dB + pfRow*128 + (kb ^ pfSw)) = pf[c2];
                *reinterpret_cast<uint4*>(dB + (64+pfRow)*128 + (kb ^ pfSw)) = pf[4+c2];
            }
            if (tid < 64)
                *reinterpret_cast<float*>(smem + HB_SQ + (nc & 1)*256 + tid*4) = pfsq;
        }
        __syncthreads();
    }

    // final flush
    #pragma unroll 1
    for (int e = 0; e < cnt; e++) {
        u64 pk;
        asm("ld.shared.b64 %0,[%1];" : "=l"(pk) : "r"(bufA + (u32)e * 1024u));
        insert_ti24(tv, tiB, __uint_as_float((u32)(pk >> 32)), (int)(u32)pk);
    }

    const size_t q = (size_t)b*NP + qb*128 + tid;
    #pragma unroll
    for (int k = 0; k < KH; k++) {
        int idx;
        asm volatile("ld.shared.b32 %0,[%1];" : "=r"(idx) : "r"(tiB + k*128u));
        d_scI24[(q*NSH + s)*KH + k] = idx;
    }
}

// ---------------- rerank: exact fp32 top-20 over 48 HMMA candidates --------
__global__ void __launch_bounds__(128) rerank_kernel() {
    const int i = blockIdx.x * 128 + threadIdx.x;   // b*NP+n
    const int b = i >> 13;

    u64 qp[32];
    {
        const ulonglong2* qr = reinterpret_cast<const ulonglong2*>(d_hfT + (size_t)i * DD);
        #pragma unroll
        for (int j = 0; j < 16; j++) { ulonglong2 w = qr[j]; qp[2*j] = w.x; qp[2*j+1] = w.y; }
    }

    float tv[KK]; int ti[KK];
    #pragma unroll
    for (int k = 0; k < KK; k++) { tv[k] = -INFINITY; ti[k] = 0x7FFFFFFF; }

    const size_t base = (size_t)i * NSH * KH;
    #pragma unroll 1
    for (int e = 0; e < NSH*KH; e++) {
        int idx = d_scI24[base + e];
        const ulonglong2* cr =
            reinterpret_cast<const ulonglong2*>(d_hfT + ((size_t)(b*NP) + idx) * DD);
        u64 a0 = 0ull, a1 = 0ull, a2 = 0ull, a3 = 0ull;
        #pragma unroll
        for (int j = 0; j < 16; j++) {          // FULL 64 channels (16 x 16B)
            ulonglong2 w = cr[j];
            if ((j & 1) == 0) { a0 = ffma2(qp[2*j], w.x, a0); a1 = ffma2(qp[2*j+1], w.y, a1); }
            else              { a2 = ffma2(qp[2*j], w.x, a2); a3 = ffma2(qp[2*j+1], w.y, a3); }
        }
        U64F2 r; r.u = fadd2(fadd2(a0, a1), fadd2(a2, a3));
        float dot = r.f.x + r.f.y;
        float v = fmaf(2.f, dot, -d_sqn[b*NP + idx]);

        // total-order insert: (value desc, index asc)
        #pragma unroll
        for (int p = 0; p < KK; p++) {
            bool sw = (v > tv[p]) || (v == tv[p] && idx < ti[p]);
            float ov = tv[p]; int oi = ti[p];
            tv[p] = sw ? v : ov;  ti[p] = sw ? idx : oi;
            v = sw ? ov : v;      idx = sw ? oi : idx;
        }
    }
    #pragma unroll
    for (int k = 0; k < KK; k++) d_nidx[(size_t)i*KK + k] = ti[k];
}

// ---------------- gather-max + BN + lrelu -> h (channel-major output) ------
__global__ void gather_kernel(const float* __restrict__ gamma,
                              const float* __restrict__ beta,
                              const float* __restrict__ mean,
                              const float* __restrict__ var,
                              float* __restrict__ out) {
    int b = blockIdx.y;
    int j = threadIdx.x >> 6;
    int o = threadIdx.x & 63;
    int n = blockIdx.x * 4 + j;

    __shared__ int sIdx[4 * KK];
    if (threadIdx.x < 4 * KK) {
        int jj = threadIdx.x / KK, kk = threadIdx.x % KK;
        sIdx[threadIdx.x] = d_nidx[((size_t)b*NP + blockIdx.x*4 + jj)*KK + kk];
    }
    __syncthreads();

    const float* Gb = d_G + (size_t)b * NP * DD;
    float mx = -INFINITY;
    #pragma unroll
    for (int k = 0; k < KK; k++)
        mx = fmaxf(mx, Gb[(size_t)sIdx[j*KK + k] * DD + o]);

    float z = d_A[((size_t)b*NP + n)*DD + o] + mx;
    float sc = gamma[o] * rsqrtf(var[o] + EPSB);
    z = (z - mean[o]) * sc + beta[o];
    z = (z >= 0.f) ? z : 0.2f * z;
    out[((size_t)b*DD + o)*NP + n] = z;
}

// ---------------- fuse: hf = elu(Wf * [h; rep]) -> point-major --------------
// Also emits fp16 hi/lo split and squared norms (replaces sqsplit_kernel).
__global__ void fuse_kernel(const float* __restrict__ h,
                            const float* __restrict__ rep,
                            const float* __restrict__ W) {
    int b = blockIdx.y;
    int n0 = blockIdx.x * 16;
    int o = threadIdx.x;          // 0..63

    __shared__ float sWT[128][64];
    __shared__ float sIn[128][16];
    __shared__ float sRed[2][16];
    for (int t = threadIdx.x; t < 128*64; t += 64) {
        int c = t >> 6, oo = t & 63;
        sWT[c][oo] = W[oo*128 + c];
    }
    for (int t = threadIdx.x; t < 128*16; t += 64) {
        int c = t >> 4, p = t & 15;
        sIn[c][p] = (c < 64) ? h  [((size_t)b*DD + c)*NP + n0 + p]
                             : rep[((size_t)b*DD + (c-64))*NP + n0 + p];
    }
    __syncthreads();

    float acc[16];
    #pragma unroll
    for (int p = 0; p < 16; p++) acc[p] = 0.f;
    for (int c = 0; c < 128; c++) {
        float w = sWT[c][o];
        #pragma unroll
        for (int p = 0; p < 16; p++) acc[p] = fmaf(w, sIn[c][p], acc[p]);
    }
    #pragma unroll
    for (int p = 0; p < 16; p++) {
        float z = acc[p];
        z = (z > 0.f) ? z : expm1f(z);
        acc[p] = z;
        size_t eoff = ((size_t)b*NP + n0 + p)*DD + o;
        d_hfT[eoff] = z;
        __half hb = __float2half(z);
        __half lb = __float2half(z - __half2float(hb));
        d_fhi[eoff] = hb;
        d_flo[eoff] = lb;
    }
    // squared norms: reduce z^2 over the 64 channels (2 warps)
    #pragma unroll
    for (int p = 0; p < 16; p++) {
        float v = acc[p] * acc[p];
        #pragma unroll
        for (int off = 16; off > 0; off >>= 1)
            v += __shfl_xor_sync(0xffffffffu, v, off);
        if ((o & 31) == 0) sRed[o >> 5][p] = v;
    }
    __syncthreads();
    if (o < 16)
        d_sqn[b*NP + n0 + o] = sRed[0][o] + sRed[1][o];
}

// ---------------- G/A from hfT (W is 64x128) ----------------
__global__ void ga_kernel(const float* __restrict__ W) {
    int b = blockIdx.y;
    int n0 = blockIdx.x * 16;
    int o = threadIdx.x;

    __shared__ float sWT[64][128];
    __shared__ float sIn[16][64];
    for (int c = 0; c < 64; c++) {
        float w = (o < 64) ? W[o*128 + c]
                           : (W[(o-64)*128 + 64 + c] - W[(o-64)*128 + c]);
        sWT[c][o] = w;
    }
    for (int t = threadIdx.x; t < 16*64; t += 128) {
        int p = t >> 6, c = t & 63;
        sIn[p][c] = d_hfT[((size_t)b*NP + n0 + p)*DD + c];
    }
    __syncthreads();

    float acc[16];
    #pragma unroll
    for (int p = 0; p < 16; p++) acc[p] = 0.f;
    for (int c = 0; c < 64; c++) {
        float w = sWT[c][o];
        #pragma unroll
        for (int p = 0; p < 16; p++) acc[p] = fmaf(w, sIn[p][c], acc[p]);
    }
    float* dst = (o < 64) ? d_G : d_A;
    int oo = o & 63;
    #pragma unroll
    for (int p = 0; p < 16; p++)
        dst[((size_t)b*NP + n0 + p)*DD + oo] = acc[p];
}

// ---------------- launch ----------------
extern "C" void kernel_launch(void* const* d_in, const int* in_sizes, int n_in,
                              void* d_out, int out_size) {
    (void)in_sizes; (void)n_in; (void)out_size;
    const float* x     = (const float*)d_in[0];
    const float* reps  = (const float*)d_in[1];
    const float* w0    = (const float*)d_in[2];
    const float* convw = (const float*)d_in[3];
    const float* gam   = (const float*)d_in[4];
    const float* bet   = (const float*)d_in[5];
    const float* rm    = (const float*)d_in[6];
    const float* rv    = (const float*)d_in[7];
    const float* fw    = (const float*)d_in[8];
    float* out = (float*)d_out;
    const size_t LSZ = (size_t)NB * DD * NP;

    cudaFuncSetAttribute(knnH_kernel,
                         cudaFuncAttributeMaxDynamicSharedMemorySize, SMEMH);

    // layer 0 (fp32 path)
    prep_x_kernel<<<NB*NP/256, 256>>>(x);
    ga0_kernel<<<dim3(NP/16, NB), 128>>>(w0);
    knn3_kernel<4><<<dim3(NP/256, NS, NB), 256>>>();
    merge_kernel<<<NB*NP/256, 256>>>();
    gather_kernel<<<dim3(NP/4, NB), 256>>>(gam, bet, rm, rv, out);

    // layers 1..3 (HMMA candidates + exact fp32 rerank)
    for (int i = 0; i < 3; i++) {
        fuse_kernel<<<dim3(NP/16, NB), 64>>>(out + (size_t)i * LSZ,
                                             reps + (size_t)i * LSZ,
                                             fw + (size_t)i * 64 * 128);
        ga_kernel<<<dim3(NP/16, NB), 128>>>(convw + (size_t)i * 64 * 128);
        knnH_kernel<<<dim3(NB*64, NSH), 128, SMEMH>>>();
        rerank_kernel<<<NB*NP/128, 128>>>();
        gather_kernel<<<dim3(NP/4, NB), 256>>>(gam + (i+1)*64, bet + (i+1)*64,
                                               rm + (i+1)*64, rv + (i+1)*64,
                                               out + (size_t)(i+1) * LSZ);
    }
}